// round 17
// baseline (speedup 1.0000x reference)
#include <cuda_runtime.h>
#include <cuda_fp16.h>
#include <cstdint>
#include <math.h>

#define Nn 8192
#define NH 64
#define NC 8
#define MAXE (Nn * 32)

// ------------------------- device scratch (static, no allocs) ----------------
__device__ __half g_S1h[Nn * NH];
__device__ __half g_S2h[Nn * NH];
__device__ float  g_S3[Nn * NC];
__device__ __half g_W1T_hi[NH * Nn];
__device__ int   g_cnt[Nn];
__device__ int   g_off[Nn];
__device__ int   g_rowptr[Nn + 1];
__device__ int   g_cols[MAXE];
__device__ float g_vals[MAXE];

#define SWZ(o)  ((o) ^ (((o) >> 3) & 0x70))

// ------------------------- HMMA / async helpers ------------------------------
__device__ __forceinline__ void mma16816(float c[4], const uint32_t a[4],
                                         uint32_t b0, uint32_t b1) {
    asm volatile(
        "mma.sync.aligned.m16n8k16.row.col.f32.f16.f16.f32 "
        "{%0,%1,%2,%3}, {%4,%5,%6,%7}, {%8,%9}, {%0,%1,%2,%3};"
        : "+f"(c[0]), "+f"(c[1]), "+f"(c[2]), "+f"(c[3])
        : "r"(a[0]), "r"(a[1]), "r"(a[2]), "r"(a[3]), "r"(b0), "r"(b1));
}

__device__ __forceinline__ void ldsm_x4(uint32_t& r0, uint32_t& r1,
                                        uint32_t& r2, uint32_t& r3, uint32_t addr) {
    asm volatile("ldmatrix.sync.aligned.m8n8.x4.shared.b16 {%0,%1,%2,%3}, [%4];"
                 : "=r"(r0), "=r"(r1), "=r"(r2), "=r"(r3) : "r"(addr));
}

__device__ __forceinline__ void cp_async16(uint32_t dst, const void* src) {
    asm volatile("cp.async.cg.shared.global [%0], [%1], 16;" :: "r"(dst), "l"(src));
}
__device__ __forceinline__ void cp_commit() {
    asm volatile("cp.async.commit_group;");
}
template <int N>
__device__ __forceinline__ void cp_wait() {
    asm volatile("cp.async.wait_group %0;" :: "n"(N));
}

__device__ __forceinline__ uint32_t pack_h2(float x, float y) {
    __half2 h = __floats2half2_rn(x, y);
    return *reinterpret_cast<uint32_t*>(&h);
}

// ------------------------- prologue: W1 transpose + zero S1h/cnt/off + out ---
// grid 256 x 256 threads. Block b transposes W1 rows [b*32, b*32+32);
// global thread i zeros one uint4 of g_S1h (65536 total), cnt/off (i<Nn),
// out (i<NC).
__global__ void prologue_kernel(const float* __restrict__ W1,
                                const float* __restrict__ blin,
                                float* __restrict__ out) {
    __shared__ float t[32][65];
    int tid = threadIdx.x;
    int gi = blockIdx.x * blockDim.x + tid;          // 0..65535
    // zero S1h (1MB as uint4)
    reinterpret_cast<uint4*>(g_S1h)[gi] = make_uint4(0, 0, 0, 0);
    if (gi < Nn) { g_cnt[gi] = 0; g_off[gi] = 0; }
    if (gi < NC) out[gi] = blin[0];
    // transpose slice
    int k0 = blockIdx.x * 32;
    #pragma unroll
    for (int i = 0; i < 8; i++) {
        int j = tid + i * 256;
        int r = j >> 6, c = j & 63;
        t[r][c] = W1[(size_t)(k0 + r) * NH + c];
    }
    __syncthreads();
    #pragma unroll
    for (int i = 0; i < 8; i++) {
        int j = tid + i * 256;
        int c = j >> 5, r = j & 31;
        g_W1T_hi[(size_t)c * Nn + k0 + r] = __float2half_rn(t[r][c]);
    }
}

// ------------------------- hist (vectorized, 8/thread) -----------------------
__global__ void hist_kernel(const int* __restrict__ row, int E) {
    int i = (blockIdx.x * blockDim.x + threadIdx.x) * 8;
    if (i + 7 < E) {
        int4 r0 = *reinterpret_cast<const int4*>(row + i);
        int4 r1 = *reinterpret_cast<const int4*>(row + i + 4);
        atomicAdd(&g_cnt[r0.x], 1); atomicAdd(&g_cnt[r0.y], 1);
        atomicAdd(&g_cnt[r0.z], 1); atomicAdd(&g_cnt[r0.w], 1);
        atomicAdd(&g_cnt[r1.x], 1); atomicAdd(&g_cnt[r1.y], 1);
        atomicAdd(&g_cnt[r1.z], 1); atomicAdd(&g_cnt[r1.w], 1);
    } else {
        for (int j = i; j < E; j++) atomicAdd(&g_cnt[row[j]], 1);
    }
}

// ------------------------- shfl exclusive scan (1024 threads) ----------------
__global__ void scan_kernel() {
    __shared__ int wsum[32];
    int t = threadIdx.x, lane = t & 31, w = t >> 5;
    int base = t * 8;
    int s = 0;
    #pragma unroll
    for (int i = 0; i < 8; i++) s += g_cnt[base + i];
    int incl = s;
    #pragma unroll
    for (int o = 1; o < 32; o <<= 1) {
        int v = __shfl_up_sync(0xFFFFFFFFu, incl, o);
        if (lane >= o) incl += v;
    }
    if (lane == 31) wsum[w] = incl;
    __syncthreads();
    if (w == 0) {
        int v = wsum[lane];
        int iw = v;
        #pragma unroll
        for (int o = 1; o < 32; o <<= 1) {
            int u = __shfl_up_sync(0xFFFFFFFFu, iw, o);
            if (lane >= o) iw += u;
        }
        wsum[lane] = iw - v;
    }
    __syncthreads();
    int acc = incl - s + wsum[w];
    #pragma unroll
    for (int i = 0; i < 8; i++) { g_rowptr[base + i] = acc; acc += g_cnt[base + i]; }
    if (t == 1023) g_rowptr[Nn] = acc;
}

__global__ void scatter_kernel(const int* __restrict__ row, const int* __restrict__ col,
                               const float* __restrict__ val, int E) {
    int e = blockIdx.x * blockDim.x + threadIdx.x;
    if (e < E) {
        int r = row[e];
        int p = g_rowptr[r] + atomicAdd(&g_off[r], 1);
        g_cols[p] = col[e];
        g_vals[p] = val[e];
    }
}

// ------------------------- HMMA GEMM1 (R11 pipeline, fp16 atomic epilogue) ---
// S1h += x @ W1 (half2 atomicAdd into zeroed g_S1h; 4 addends/elem).
// K split x4 (grid 512, 2 CTAs/SM). 4 stages x 25.6KB, prefetch 3,
// wait_group 2, commit every iteration. A via cp.async fp32 swizzled smem;
// B (144B padded rows) via ldmatrix.x4.
#define SLAB0 25600
__global__ void __launch_bounds__(256, 2)
gemm1_hmma(const float* __restrict__ Aext) {
    extern __shared__ char smem[];
    const uint32_t sb = (uint32_t)__cvta_generic_to_shared(smem);
    const int tid = threadIdx.x, lane = tid & 31, w = tid >> 5;
    const int wm = (w & 3) * 16, wn = (w >> 2) * 32;
    const int g = lane >> 2, tg = lane & 3;

    float acc[4][4];
    #pragma unroll
    for (int nt = 0; nt < 4; nt++)
        #pragma unroll
        for (int q = 0; q < 4; q++) acc[nt][q] = 0.f;

    uint32_t aoff[16];
    #pragma unroll
    for (int ks = 0; ks < 4; ks++)
        #pragma unroll
        for (int i = 0; i < 4; i++) {
            uint32_t o = (uint32_t)((wm + g + (i & 1) * 8) * 256 +
                                    ks * 64 + tg * 8 + (i >> 1) * 32);
            aoff[ks * 4 + i] = SWZ(o);
        }

    const int m0 = (blockIdx.x >> 2) * 64;
    const int kq = blockIdx.x & 3;
    const float* abase = Aext + (size_t)(m0 + (tid >> 4)) * Nn + kq * 2048 + (tid & 15) * 4;
    const uint32_t adst0 = SWZ((uint32_t)((tid >> 4) * 256 + (tid & 15) * 16));
    const __half* bbase = g_W1T_hi + (size_t)(tid >> 3) * Nn + kq * 2048 + (tid & 7) * 8;
    const uint32_t bdst0 = 16384u + (tid >> 3) * 144 + (tid & 7) * 16;
    const uint32_t lmb = 16384u +
        (uint32_t)((wn + ((lane >> 4) * 8) + (lane & 7)) * 144 + ((lane >> 3) & 1) * 16);

    auto issue = [&](int kc) {
        uint32_t dbase = sb + (kc & 3) * SLAB0;
        const float* as = abase + kc * 64;
        #pragma unroll
        for (int ii = 0; ii < 4; ii++)
            cp_async16(dbase + adst0 + ii * 4096, as + ii * 16 * Nn);
        const __half* bs = bbase + kc * 64;
        #pragma unroll
        for (int ii = 0; ii < 2; ii++)
            cp_async16(dbase + bdst0 + ii * 32 * 144, bs + ii * 32 * Nn);
    };

    issue(0); cp_commit();
    issue(1); cp_commit();
    issue(2); cp_commit();
    #pragma unroll 1
    for (int kc = 0; kc < 32; kc++) {
        cp_wait<2>();
        __syncthreads();
        if (kc + 3 < 32) issue(kc + 3);
        cp_commit();
        const char* base = smem + (kc & 3) * SLAB0;
        const uint32_t bb = sb + (kc & 3) * SLAB0 + lmb;
        #pragma unroll
        for (int ks = 0; ks < 4; ks++) {
            uint32_t ah[4];
            #pragma unroll
            for (int i = 0; i < 4; i++) {
                float2 v = *reinterpret_cast<const float2*>(base + aoff[ks * 4 + i]);
                ah[i] = pack_h2(v.x, v.y);
            }
            uint32_t b00, b01, b10, b11, b20, b21, b30, b31;
            ldsm_x4(b00, b01, b10, b11, bb + ks * 32);
            ldsm_x4(b20, b21, b30, b31, bb + ks * 32 + 2304);
            mma16816(acc[0], ah, b00, b01);
            mma16816(acc[1], ah, b10, b11);
            mma16816(acc[2], ah, b20, b21);
            mma16816(acc[3], ah, b30, b31);
        }
    }
    #pragma unroll
    for (int nt = 0; nt < 4; nt++) {
        int row = m0 + wm + g;
        int col = wn + nt * 8 + 2 * tg;
        atomicAdd(reinterpret_cast<__half2*>(g_S1h + (size_t)row * 64 + col),
                  __floats2half2_rn(acc[nt][0], acc[nt][1]));
        atomicAdd(reinterpret_cast<__half2*>(g_S1h + (size_t)(row + 8) * 64 + col),
                  __floats2half2_rn(acc[nt][2], acc[nt][3]));
    }
}

// ------------------------- SpMM1 (fp16 gathers, unroll 8) + GEMM2 ------------
__global__ void spmm1_g2(const float* __restrict__ b1, const float* __restrict__ W2) {
    __shared__ float w2s[NH * NH];
    int tid = threadIdx.x;
    #pragma unroll
    for (int i = 0; i < 16; i++) w2s[tid + i * 256] = W2[tid + i * 256];
    __syncthreads();
    int gt = blockIdx.x * blockDim.x + tid;
    int row = gt >> 5, lane = gt & 31;
    int s = g_rowptr[row], e = g_rowptr[row + 1];
    const __half2* S = reinterpret_cast<const __half2*>(g_S1h);
    float a0 = 0.f, a1 = 0.f;
    int i = s;
    for (; i + 8 <= e; i += 8) {
        float2 f[8];
        #pragma unroll
        for (int j = 0; j < 8; j++)
            f[j] = __half22float2(S[(size_t)g_cols[i + j] * 32 + lane]);
        #pragma unroll
        for (int j = 0; j < 8; j++) {
            float v = g_vals[i + j];
            a0 += v * f[j].x; a1 += v * f[j].y;
        }
    }
    for (; i < e; i++) {
        float2 f = __half22float2(S[(size_t)g_cols[i] * 32 + lane]);
        float v = g_vals[i];
        a0 += v * f.x; a1 += v * f.y;
    }
    float2 bb = *reinterpret_cast<const float2*>(b1 + 2 * lane);
    float r0 = fmaxf(a0 + bb.x, 0.f);
    float r1 = fmaxf(a1 + bb.y, 0.f);
    float acc0 = 0.f, acc1 = 0.f;
    #pragma unroll
    for (int j = 0; j < 32; j++) {
        float hk0 = __shfl_sync(0xFFFFFFFFu, r0, j);
        float hk1 = __shfl_sync(0xFFFFFFFFu, r1, j);
        float2 wa = *reinterpret_cast<const float2*>(w2s + (2 * j) * 64 + 2 * lane);
        float2 wb = *reinterpret_cast<const float2*>(w2s + (2 * j + 1) * 64 + 2 * lane);
        acc0 += hk0 * wa.x + hk1 * wb.x;
        acc1 += hk0 * wa.y + hk1 * wb.y;
    }
    reinterpret_cast<__half2*>(g_S2h)[(size_t)row * 32 + lane] =
        __floats2half2_rn(acc0, acc1);
}

// ------------------------- SpMM2 (fp16 gathers, unroll 8) + gemm3 ------------
__global__ void spmm2_g3(const float* __restrict__ b2, const float* __restrict__ W3) {
    __shared__ float w3t[NC * NH];
    int tid = threadIdx.x;
    #pragma unroll
    for (int ii = 0; ii < 2; ii++) {
        int i = tid + ii * 256;
        w3t[(i & 7) * 64 + (i >> 3)] = W3[i];
    }
    __syncthreads();
    int gt = blockIdx.x * blockDim.x + tid;
    int row = gt >> 5, lane = gt & 31;
    int s = g_rowptr[row], e = g_rowptr[row + 1];
    const __half2* S = reinterpret_cast<const __half2*>(g_S2h);
    float a0 = 0.f, a1 = 0.f;
    int i = s;
    for (; i + 8 <= e; i += 8) {
        float2 f[8];
        #pragma unroll
        for (int j = 0; j < 8; j++)
            f[j] = __half22float2(S[(size_t)g_cols[i + j] * 32 + lane]);
        #pragma unroll
        for (int j = 0; j < 8; j++) {
            float v = g_vals[i + j];
            a0 += v * f[j].x; a1 += v * f[j].y;
        }
    }
    for (; i < e; i++) {
        float2 f = __half22float2(S[(size_t)g_cols[i] * 32 + lane]);
        float v = g_vals[i];
        a0 += v * f.x; a1 += v * f.y;
    }
    float2 bb = *reinterpret_cast<const float2*>(b2 + 2 * lane);
    float r0 = fmaxf(a0 + bb.x, 0.f);
    float r1 = fmaxf(a1 + bb.y, 0.f);
    float p[NC];
    #pragma unroll
    for (int f = 0; f < NC; f++) {
        float2 wv = *reinterpret_cast<const float2*>(w3t + f * 64 + 2 * lane);
        p[f] = r0 * wv.x + r1 * wv.y;
    }
    #pragma unroll
    for (int o = 16; o > 0; o >>= 1)
        #pragma unroll
        for (int f = 0; f < NC; f++) p[f] += __shfl_xor_sync(0xFFFFFFFFu, p[f], o);
    if (lane == 0) {
        float* o8 = g_S3 + (size_t)row * NC;
        *reinterpret_cast<float4*>(o8)     = make_float4(p[0], p[1], p[2], p[3]);
        *reinterpret_cast<float4*>(o8 + 4) = make_float4(p[4], p[5], p[6], p[7]);
    }
}

// ------------------------- final: warp-per-row spmm8 + softmax + head --------
__global__ void final_fused(const float* __restrict__ b3, const float* __restrict__ Wlin,
                            float* __restrict__ out) {
    __shared__ float red[8][NC];
    int t = threadIdx.x, lane = t & 31, wp = t >> 5;
    int row = blockIdx.x * 8 + wp;
    float acc[NC];
    #pragma unroll
    for (int f = 0; f < NC; f++) acc[f] = 0.f;
    int s = g_rowptr[row], e = g_rowptr[row + 1];
    for (int i = s + lane; i < e; i += 32) {
        int c = g_cols[i];
        float v = g_vals[i];
        const float4* p = reinterpret_cast<const float4*>(g_S3 + (size_t)c * NC);
        float4 q0 = p[0], q1 = p[1];
        acc[0] += v * q0.x; acc[1] += v * q0.y; acc[2] += v * q0.z; acc[3] += v * q0.w;
        acc[4] += v * q1.x; acc[5] += v * q1.y; acc[6] += v * q1.z; acc[7] += v * q1.w;
    }
    #pragma unroll
    for (int o = 16; o > 0; o >>= 1)
        #pragma unroll
        for (int f = 0; f < NC; f++) acc[f] += __shfl_xor_sync(0xFFFFFFFFu, acc[f], o);
    if (lane == 0) {
        float h[NC];
        #pragma unroll
        for (int f = 0; f < NC; f++) h[f] = acc[f] + b3[f];
        float m = h[0];
        #pragma unroll
        for (int f = 1; f < NC; f++) m = fmaxf(m, h[f]);
        float ssum = 0.f;
        #pragma unroll
        for (int f = 0; f < NC; f++) ssum += expf(h[f] - m);
        float lse = m + logf(ssum);
        float wv = Wlin[row];
        #pragma unroll
        for (int f = 0; f < NC; f++) red[wp][f] = (h[f] - lse) * wv;
    }
    __syncthreads();
    if (t < NC) {
        float ssum = 0.f;
        #pragma unroll
        for (int j = 0; j < 8; j++) ssum += red[j][t];
        atomicAdd(&out[t], ssum);
    }
}

// ------------------------- launch -------------------------------------------
extern "C" void kernel_launch(void* const* d_in, const int* in_sizes, int n_in,
                              void* d_out, int out_size) {
    const float* x    = (const float*)d_in[0];
    const int*   arow = (const int*)d_in[1];
    const int*   acol = (const int*)d_in[2];
    const float* aval = (const float*)d_in[3];
    const float* W1   = (const float*)d_in[4];
    const float* b1   = (const float*)d_in[5];
    const float* W2   = (const float*)d_in[6];
    const float* b2   = (const float*)d_in[7];
    const float* W3   = (const float*)d_in[8];
    const float* b3   = (const float*)d_in[9];
    const float* Wlin = (const float*)d_in[10];
    const float* blin = (const float*)d_in[11];
    const int E = in_sizes[1];
    float* out = (float*)d_out;

    static cudaStream_t s_side = nullptr;
    static cudaEvent_t ev_fork, ev_join;
    if (!s_side) {
        cudaStreamCreateWithFlags(&s_side, cudaStreamNonBlocking);
        cudaEventCreateWithFlags(&ev_fork, cudaEventDisableTiming);
        cudaEventCreateWithFlags(&ev_join, cudaEventDisableTiming);
        cudaFuncSetAttribute(gemm1_hmma, cudaFuncAttributeMaxDynamicSharedMemorySize,
                             4 * SLAB0);
    }

    // main stream: merged prologue (W1 transpose + zero S1h/cnt/off + out init)
    prologue_kernel<<<256, 256>>>(W1, blin, out);
    cudaEventRecord(ev_fork, 0);

    // side stream: CSR build (overlaps GEMM1)
    cudaStreamWaitEvent(s_side, ev_fork, 0);
    hist_kernel<<<(E / 8 + 255) / 256, 256, 0, s_side>>>(arow, E);
    scan_kernel<<<1, 1024, 0, s_side>>>();
    scatter_kernel<<<(E + 255) / 256, 256, 0, s_side>>>(arow, acol, aval, E);
    cudaEventRecord(ev_join, s_side);

    // main stream: GEMM1 (fp16 atomic epilogue)
    gemm1_hmma<<<4 * Nn / 64, 256, 4 * SLAB0>>>(x);

    // join, then the spmm chain
    cudaStreamWaitEvent(0, ev_join, 0);
    spmm1_g2<<<(Nn * 32) / 256, 256>>>(b1, W2);
    spmm2_g3<<<(Nn * 32) / 256, 256>>>(b2, W3);
    final_fused<<<Nn / 8, 256>>>(b3, Wlin, out);
}